// round 17
// baseline (speedup 1.0000x reference)
#include <cuda_runtime.h>
#include <cstdint>

#define N_NODES 8192
#define IN_F 128
#define OUT_F 64
#define ROWS_PB 16   // rows per k_linear block

// Scratch (allocation-free rule: __device__ globals)
__device__ float g_z[N_NODES * OUT_F];   // z = X @ W^T + b
__device__ float g_wo[N_NODES];          // exp(lrelu(zi))
__device__ float g_wd[N_NODES];          // exp(lrelu(zi+zj))

__device__ __forceinline__ float lrelu(float x) {
    return x > 0.0f ? x : 0.01f * x;
}

// Kernel 1: z = X @ W^T + b + attention scalars. W staged in padded smem;
// 4 independent FFMA accumulators break the serial dependency chain
// (512 -> 128 cyc per row-group).
__global__ void __launch_bounds__(256) k_linear(
    const float* __restrict__ X, const float* __restrict__ W,
    const float* __restrict__ bias, const float* __restrict__ a1,
    const float* __restrict__ a2)
{
    __shared__ float ws[OUT_F * 132];
    __shared__ float xs[4][IN_F];
    __shared__ float s1[8], s2[8];

    const int tid  = threadIdx.x;
    const int grp  = tid >> 6;      // 0..3 row within group
    const int c    = tid & 63;      // output feature
    const int wid  = tid >> 5;
    const int lane = tid & 31;

    // Stage W (coalesced global reads, padded smem rows: stride 132 words ->
    // (33c mod 8) distinct per 8-lane phase -> conflict-free LDS.128)
    for (int i = tid; i < OUT_F * IN_F; i += 256) {
        int cc = i >> 7, kk = i & 127;
        ws[cc * 132 + kk] = W[i];
    }
    const float bc  = bias[c];
    const float a1c = a1[c];
    const float a2c = a2[c];
    __syncthreads();

    const float4* wv4 = (const float4*)(ws + c * 132);

#pragma unroll 1
    for (int rg = 0; rg < ROWS_PB / 4; rg++) {
        const int row = blockIdx.x * ROWS_PB + rg * 4 + grp;
        xs[grp][c]      = X[row * IN_F + c];
        xs[grp][c + 64] = X[row * IN_F + 64 + c];
        __syncthreads();

        float ac0 = bc, ac1 = 0.0f, ac2 = 0.0f, ac3 = 0.0f;
#pragma unroll
        for (int k = 0; k < IN_F / 16; k++) {   // 8 macro-steps, 4 streams
            float4 w0 = wv4[4 * k + 0];
            float4 w1 = wv4[4 * k + 1];
            float4 w2 = wv4[4 * k + 2];
            float4 w3 = wv4[4 * k + 3];
            const float* x = xs[grp] + 16 * k;
            ac0 = fmaf(w0.x, x[0],  ac0); ac0 = fmaf(w0.y, x[1],  ac0);
            ac0 = fmaf(w0.z, x[2],  ac0); ac0 = fmaf(w0.w, x[3],  ac0);
            ac1 = fmaf(w1.x, x[4],  ac1); ac1 = fmaf(w1.y, x[5],  ac1);
            ac1 = fmaf(w1.z, x[6],  ac1); ac1 = fmaf(w1.w, x[7],  ac1);
            ac2 = fmaf(w2.x, x[8],  ac2); ac2 = fmaf(w2.y, x[9],  ac2);
            ac2 = fmaf(w2.z, x[10], ac2); ac2 = fmaf(w2.w, x[11], ac2);
            ac3 = fmaf(w3.x, x[12], ac3); ac3 = fmaf(w3.y, x[13], ac3);
            ac3 = fmaf(w3.z, x[14], ac3); ac3 = fmaf(w3.w, x[15], ac3);
        }
        float acc = (ac0 + ac1) + (ac2 + ac3);
        g_z[row * OUT_F + c] = acc;

        float p1 = a1c * acc;
        float p2 = a2c * acc;
#pragma unroll
        for (int off = 16; off > 0; off >>= 1) {
            p1 += __shfl_down_sync(0xFFFFFFFFu, p1, off);
            p2 += __shfl_down_sync(0xFFFFFFFFu, p2, off);
        }
        if (lane == 0) { s1[wid] = p1; s2[wid] = p2; }
        __syncthreads();
        if (c == 0) {
            float zi = s1[2 * grp] + s1[2 * grp + 1];
            float zj = s2[2 * grp] + s2[2 * grp + 1];
            g_wo[row] = expf(lrelu(zi));
            g_wd[row] = expf(lrelu(zi + zj));
        }
    }
}

// Kernel 2: one warp per row. Software-pipelined A stream; min-blocks=5 forces
// ~51 regs -> 40 warps/SM (62.5% occ) for more in-flight bytes. Epilogue
// operands loaded AFTER the loop (L2-hot; fewer live regs in the mainloop).
__global__ void __launch_bounds__(256, 5) k_attn(
    const float* __restrict__ A, float* __restrict__ out)
{
    const int warp = threadIdx.x >> 5;
    const int lane = threadIdx.x & 31;
    const int row  = blockIdx.x * 8 + warp;

    const float4* arow = (const float4*)(A + (size_t)row * N_NODES);

    float a0 = 0.0f, a1v = 0.0f;    // gather accumulators (pair A)
    float b0 = 0.0f, b1v = 0.0f;    // gather accumulators (pair B)
    float dg0 = 0.0f, dg1 = 0.0f;   // degree accumulators (FMA pipe, exact)

    // Prologue prefetch
    float4 n0 = __ldcs(&arow[0 * 32 + lane]);
    float4 n1 = __ldcs(&arow[1 * 32 + lane]);
    float4 n2 = __ldcs(&arow[2 * 32 + lane]);
    float4 n3 = __ldcs(&arow[3 * 32 + lane]);

#pragma unroll 1
    for (int it = 0; it < 16; ++it) {
        float4 v0 = n0, v1 = n1, v2 = n2, v3 = n3;
        if (it < 15) {
            const float4* p = arow + (it + 1) * 128;
            n0 = __ldcs(&p[0 * 32 + lane]);
            n1 = __ldcs(&p[1 * 32 + lane]);
            n2 = __ldcs(&p[2 * 32 + lane]);
            n3 = __ldcs(&p[3 * 32 + lane]);
        }
        const int base = it * 512;

#pragma unroll
        for (int k = 0; k < 4; k++) {
            float4 v = (k == 0) ? v0 : (k == 1) ? v1 : (k == 2) ? v2 : v3;
            const int cb = base + k * 128;
            dg0 += v.x + v.y;
            dg1 += v.z + v.w;
            unsigned mx = __ballot_sync(0xFFFFFFFFu, v.x != 0.0f);
            unsigned my = __ballot_sync(0xFFFFFFFFu, v.y != 0.0f);
            unsigned mz = __ballot_sync(0xFFFFFFFFu, v.z != 0.0f);
            unsigned mw = __ballot_sync(0xFFFFFFFFu, v.w != 0.0f);
            while (mx) { int l = __ffs(mx) - 1; mx &= mx - 1;
                const float* zr = g_z + (size_t)(cb + 4 * l + 0) * OUT_F;
                a0  += __ldg(zr + lane); a1v += __ldg(zr + lane + 32); }
            while (my) { int l = __ffs(my) - 1; my &= my - 1;
                const float* zr = g_z + (size_t)(cb + 4 * l + 1) * OUT_F;
                b0  += __ldg(zr + lane); b1v += __ldg(zr + lane + 32); }
            while (mz) { int l = __ffs(mz) - 1; mz &= mz - 1;
                const float* zr = g_z + (size_t)(cb + 4 * l + 2) * OUT_F;
                a0  += __ldg(zr + lane); a1v += __ldg(zr + lane + 32); }
            while (mw) { int l = __ffs(mw) - 1; mw &= mw - 1;
                const float* zr = g_z + (size_t)(cb + 4 * l + 3) * OUT_F;
                b0  += __ldg(zr + lane); b1v += __ldg(zr + lane + 32); }
        }
    }

    float acc0 = a0 + b0;
    float acc1 = a1v + b1v;

    // Warp-total degree (exact integers in fp32)
    float dgf = dg0 + dg1;
#pragma unroll
    for (int off = 16; off > 0; off >>= 1)
        dgf += __shfl_xor_sync(0xFFFFFFFFu, dgf, off);
    int deg = __float2int_rn(dgf);

    // Epilogue operands (L2-hot; self-loop row was gathered above)
    const float zr0 = __ldg(&g_z[row * OUT_F + lane]);
    const float zr1 = __ldg(&g_z[row * OUT_F + 32 + lane]);
    const float wo  = __ldg(&g_wo[row]);
    const float wd  = __ldg(&g_wd[row]);

    float inv = 1.0f / (wo * (float)(deg - 1) + wd);
    float az0 = (wo * (acc0 - zr0) + wd * zr0) * inv;
    float az1 = (wo * (acc1 - zr1) + wd * zr1) * inv;
    out[row * OUT_F + lane]      = fmaxf(zr0 - az0, 0.0f);
    out[row * OUT_F + 32 + lane] = fmaxf(zr1 - az1, 0.0f);
}

extern "C" void kernel_launch(void* const* d_in, const int* in_sizes, int n_in,
                              void* d_out, int out_size)
{
    // Input mapping by element count (deterministic, host-only):
    const float* X = nullptr; const float* A = nullptr; const float* W = nullptr;
    const float* sv[3] = {nullptr, nullptr, nullptr};
    int nsv = 0;
    for (int i = 0; i < n_in; i++) {
        long long sz = in_sizes[i];
        if (sz == (long long)N_NODES * N_NODES)      A = (const float*)d_in[i];
        else if (sz == (long long)N_NODES * IN_F)    X = (const float*)d_in[i];
        else if (sz == (long long)OUT_F * IN_F)      W = (const float*)d_in[i];
        else if (sz == OUT_F && nsv < 3)             sv[nsv++] = (const float*)d_in[i];
    }
    const float* b  = sv[0];
    const float* a1 = sv[1];
    const float* a2 = sv[2];
    float* out = (float*)d_out;               // [8192, 64]

    k_linear<<<N_NODES / ROWS_PB, 256>>>(X, W, b, a1, a2);
    k_attn<<<N_NODES / 8, 256>>>(A, out);
}